// round 16
// baseline (speedup 1.0000x reference)
#include <cuda_runtime.h>
#include <math.h>

#define TT  64
#define BB  16
#define II  512
#define HH  512
#define OO  512
#define NN  256
#define WD  64
#define RR  4
#define NIN 768
#define IFW 471
#define FEPS 1e-6f

// ---------------- persistent state -------------
__device__ __align__(16) float g_M [BB*NN*WD];
__device__ float g_u [2][BB*NN];               // parity double-buffered usage
__device__ float g_p [2][BB*NN];
__device__ float g_ww[BB*NN];
__device__ float g_L [2][BB*NN*NN];            // double-buffered (8MB)
__device__ float g_rw[BB*RR*NN];
__device__ __align__(16) float g_rv[BB*RR*WD];
__device__ __align__(16) float g_h [BB*HH];
__device__ float g_po [BB*OO];
__device__ float g_if [BB*IFW];
__device__ float g_fwd[BB*RR*NN];
__device__ float g_esw [BB*NN];        // exp(wb*(sim-1)) per slot
__device__ float g_esum[BB*8];         // per-chunk partial sums of e
__device__ float g_srt [BB*NN];        // usage scattered into sorted order
__device__ int   g_rank[BB*NN];        // stable argsort rank per slot
__device__ float g_rsim[BB*RR*NN];
__device__ __align__(16) float g_bA[8*BB*NN*4];  // bwd partial A (float4 per slot)
__device__ __align__(16) float g_bB[8*BB*NN*4];  // bwd partial B

__device__ __forceinline__ float sigm(float x){ return 1.f/(1.f+expf(-x)); }
__device__ __forceinline__ float oneplus(float x){ return 1.f + (x > 20.f ? x : log1pf(expf(x))); }

// ---------------- init ------------------
__global__ void k_init(){
    int i0 = blockIdx.x*blockDim.x + threadIdx.x;
    int st = gridDim.x*blockDim.x;
    for (int i=i0;i<BB*NN*NN;i+=st){ g_L[0][i]=0.f; g_L[1][i]=0.f; }
    for (int i=i0;i<BB*NN*WD;i+=st) g_M[i]=1e-6f;
    for (int i=i0;i<BB*NN;i+=st){
        g_u[0][i]=0.f; g_u[1][i]=0.f;
        g_p[0][i]=0.f; g_p[1][i]=0.f; g_ww[i]=0.f;
    }
    for (int i=i0;i<BB*RR*NN;i+=st) g_rw[i]=0.f;
    for (int i=i0;i<BB*RR*WD;i+=st) g_rv[i]=0.f;
}

// ---------------- K1: out(t-1) = po + rv@Wm  AND  h = relu([x,rv]@W_hid + b) ----
__global__ __launch_bounds__(256) void k_hidout(const float* __restrict__ x,
        const float* __restrict__ Wh, const float* __restrict__ bh,
        const float* __restrict__ Wm, float* __restrict__ out, int t){
    extern __shared__ __align__(16) float s[];
    float* sp = s + BB*NIN;
    int tid = threadIdx.x;
    for (int i=tid;i<BB*(NIN/4);i+=256){
        int b = i/(NIN/4), k4 = i - b*(NIN/4);
        float4 v = (k4 < II/4) ? reinterpret_cast<const float4*>(x + (t*BB+b)*II)[k4]
                               : reinterpret_cast<const float4*>(g_rv + b*RR*WD)[k4 - II/4];
        reinterpret_cast<float4*>(s)[b*(NIN/4) + k4] = v;
    }
    __syncthreads();

    int kg = tid>>4, jl = tid&15;
    int j = blockIdx.x*16 + jl;

    if (t > 0){
        const float* Wc = Wm + j;
        float acc[BB];
        #pragma unroll
        for (int b=0;b<BB;b++) acc[b]=0.f;
        int k0 = kg*16;
        #pragma unroll
        for (int kk=0; kk<16; kk+=4){
            int k = k0+kk;
            float w0 = Wc[(k+0)*OO], w1 = Wc[(k+1)*OO], w2 = Wc[(k+2)*OO], w3 = Wc[(k+3)*OO];
            #pragma unroll
            for (int b=0;b<BB;b++){
                float4 v = *reinterpret_cast<const float4*>(&s[b*NIN + II + k]);
                acc[b] = fmaf(v.x,w0, fmaf(v.y,w1, fmaf(v.z,w2, fmaf(v.w,w3, acc[b]))));
            }
        }
        __syncthreads();
        #pragma unroll
        for (int b=0;b<BB;b++) sp[kg*256 + b*16 + jl] = acc[b];
        __syncthreads();
        {
            int p = tid;
            int b = p>>4, jj = p&15;
            int jo = blockIdx.x*16 + jj;
            float sum = g_po[b*OO + jo];
            #pragma unroll
            for (int g=0;g<16;g++) sum += sp[g*256 + p];
            out[((t-1)*BB + b)*OO + jo] = sum;
        }
        __syncthreads();
    }

    const float* Wc = Wh + j;
    float acc[BB];
    #pragma unroll
    for (int b=0;b<BB;b++) acc[b]=0.f;
    int k0 = kg*48;
    #pragma unroll 3
    for (int kk=0; kk<48; kk+=4){
        int k = k0+kk;
        float w0 = Wc[(k+0)*HH], w1 = Wc[(k+1)*HH], w2 = Wc[(k+2)*HH], w3 = Wc[(k+3)*HH];
        #pragma unroll
        for (int b=0;b<BB;b++){
            float4 v = *reinterpret_cast<const float4*>(&s[b*NIN+k]);
            acc[b] = fmaf(v.x,w0, fmaf(v.y,w1, fmaf(v.z,w2, fmaf(v.w,w3, acc[b]))));
        }
    }
    __syncthreads();
    #pragma unroll
    for (int b=0;b<BB;b++) sp[kg*256 + b*16 + jl] = acc[b];
    __syncthreads();
    {
        int p = tid;
        int b = p>>4, jj = p&15;
        int jo = blockIdx.x*16 + jj;
        float sum = bh[jo];
        #pragma unroll
        for (int g=0;g<16;g++) sum += sp[g*256 + p];
        g_h[b*HH + jo] = fmaxf(sum, 0.f);
    }
}

// ---------------- K2: pre_out = h@W_out ; iface = h@W_iface ---------------------
__global__ __launch_bounds__(256) void k_proj(const float* __restrict__ Wo,
                                              const float* __restrict__ Wi){
    extern __shared__ __align__(16) float s[];
    float* sp = s + BB*HH;
    int tid = threadIdx.x;
    for (int i=tid;i<BB*HH/4;i+=256)
        reinterpret_cast<float4*>(s)[i] = reinterpret_cast<const float4*>(g_h)[i];
    __syncthreads();

    int kg = tid>>4, jl = tid&15;
    int j = blockIdx.x*16 + jl;
    const float* Wc; int stride;
    if (j < OO){ Wc = Wo + j; stride = OO; }
    else { int jj = j - OO; if (jj > IFW-1) jj = IFW-1; Wc = Wi + jj; stride = IFW; }
    float acc[BB];
    #pragma unroll
    for (int b=0;b<BB;b++) acc[b]=0.f;
    int k0 = kg*32;
    #pragma unroll 2
    for (int kk=0; kk<32; kk+=4){
        int k = k0+kk;
        float w0 = Wc[(k+0)*stride], w1 = Wc[(k+1)*stride];
        float w2 = Wc[(k+2)*stride], w3 = Wc[(k+3)*stride];
        #pragma unroll
        for (int b=0;b<BB;b++){
            float4 v = *reinterpret_cast<const float4*>(&s[b*HH+k]);
            acc[b] = fmaf(v.x,w0, fmaf(v.y,w1, fmaf(v.z,w2, fmaf(v.w,w3, acc[b]))));
        }
    }
    __syncthreads();
    #pragma unroll
    for (int b=0;b<BB;b++) sp[kg*256 + b*16 + jl] = acc[b];
    __syncthreads();
    {
        int p = tid;
        int b = p>>4, jj = p&15;
        int jo = blockIdx.x*16 + jj;
        float sum = 0.f;
        #pragma unroll
        for (int g=0;g<16;g++) sum += sp[g*256 + p];
        if (jo < OO) g_po[b*OO + jo] = sum;
        else if (jo - OO < IFW) g_if[b*IFW + (jo-OO)] = sum;
    }
}

// ---------------- K3: sims + distributed usage/rank (8 balanced CTAs/batch) -----
// grid (8,16) x 256. Each CTA: replicated usage update + keys; sims for its 32
// slots; ranks for its 32 slots (8 threads/slot). CTA x==0 publishes new usage.
__global__ __launch_bounds__(256) void k_wsim(int par){
    __shared__ float wk_s[64];
    __shared__ float s_un[256];
    __shared__ __align__(16) unsigned long long sk64[256];
    __shared__ float red8[8];
    int b = blockIdx.y, c = blockIdx.x;
    int tid = threadIdx.x, wi = tid>>5, l = tid&31;
    const float* ifc = g_if + b*IFW;

    if (tid < 64) wk_s[tid] = ifc[260+tid];

    // replicated usage update + key build
    float fg0 = sigm(ifc[453]), fg1 = sigm(ifc[454]);
    float fg2 = sigm(ifc[455]), fg3 = sigm(ifc[456]);
    float u   = g_u[par][b*NN + tid];
    float wwo = g_ww[b*NN + tid];
    float ret = (1.f - fg0*g_rw[(b*RR+0)*NN+tid])
              * (1.f - fg1*g_rw[(b*RR+1)*NN+tid])
              * (1.f - fg2*g_rw[(b*RR+2)*NN+tid])
              * (1.f - fg3*g_rw[(b*RR+3)*NN+tid]);
    float un = (u + wwo - u*wwo) * ret;
    s_un[tid] = un;
    unsigned int bits = __float_as_uint(un);
    bits ^= (unsigned int)(((int)bits >> 31)) | 0x80000000u;
    sk64[tid] = ((unsigned long long)bits << 32) | (unsigned int)tid;
    if (c == 0) g_u[par^1][b*NN + tid] = un;
    __syncthreads();

    // sims for this CTA's 32 slots
    float k0 = wk_s[l], k1 = wk_s[l+32];
    float kk = k0*k0 + k1*k1;
    int nb = c*32 + wi*4;
    float ns[4], dt[4];
    #pragma unroll
    for (int i=0;i<4;i++){
        const float* Mr = g_M + (b*NN + nb + i)*WD;
        float m0 = Mr[l], m1 = Mr[l+32];
        ns[i] = m0*m0 + m1*m1;
        dt[i] = m0*k0 + m1*k1;
    }
    #pragma unroll
    for (int o=16;o;o>>=1){
        kk += __shfl_xor_sync(0xffffffffu, kk, o);
        #pragma unroll
        for (int i=0;i<4;i++){
            ns[i] += __shfl_xor_sync(0xffffffffu, ns[i], o);
            dt[i] += __shfl_xor_sync(0xffffffffu, dt[i], o);
        }
    }
    if (l==0){
        float wb = oneplus(ifc[324]);
        float dk = sqrtf(kk) + FEPS;
        float psum = 0.f;
        #pragma unroll
        for (int i=0;i<4;i++){
            float sim = dt[i] / ((sqrtf(ns[i])+FEPS) * dk);
            float e = expf(wb * (sim - 1.f));
            g_esw[b*NN + nb + i] = e;
            psum += e;
        }
        red8[wi] = psum;
    }

    // ranks for this CTA's 32 slots: 8 threads per slot, 32 keys per thread
    int sl = tid>>3, ch = tid&7;
    unsigned long long mykey = sk64[c*32 + sl];
    const ulonglong2* p2 = reinterpret_cast<const ulonglong2*>(sk64);
    int r = 0;
    #pragma unroll
    for (int q=0;q<16;q++){
        ulonglong2 v = p2[ch*16 + q];
        r += (int)(v.x < mykey) + (int)(v.y < mykey);
    }
    r += __shfl_down_sync(0xffffffffu, r, 4, 8);
    r += __shfl_down_sync(0xffffffffu, r, 2, 8);
    r += __shfl_down_sync(0xffffffffu, r, 1, 8);
    __syncthreads();   // red8 (esum partials) ready
    if (ch == 0){
        int slot = c*32 + sl;
        g_srt [b*NN + r]    = s_un[slot];   // ranks are a permutation: race-free
        g_rank[b*NN + slot] = r;
    }
    if (tid == 0){
        float tot = 0.f;
        #pragma unroll
        for (int g=0;g<8;g++) tot += red8[g];
        g_esum[b*8 + c] = tot;
    }
}

// ---------------- K4: ww+alloc prologue + M update + read sims + L + fwd + bwd --
// grid (40,16) x 256. x<32: warp-per-L-row. x>=32: bwd chunk c=x-32.
__global__ __launch_bounds__(256) void k_meml(int par){
    int b = blockIdx.y;
    int tid = threadIdx.x, wi = tid>>5, l = tid&31;
    const float* ifc = g_if + b*IFW;
    __shared__ float s_ww[256];
    __shared__ float s_ex[256];
    __shared__ float red8[8];
    __shared__ float4 rk4[64];
    __shared__ float ev_s[64], wv_s[64];

    // stage iface vectors early (overlaps prologue)
    if (blockIdx.x < 32 && tid < 64){
        rk4[tid] = make_float4(ifc[tid], ifc[64+tid], ifc[128+tid], ifc[192+tid]);
        ev_s[tid] = sigm(ifc[325 + tid]);
        wv_s[tid] = ifc[389 + tid];
    }
    // ---- prologue: alloc from sorted-usage scan, then ww
    float eT  = g_esw[b*NN + tid];
    float un  = g_u[par^1][b*NN + tid];
    int   rk  = g_rank[b*NN + tid];
    float srt = g_srt[b*NN + tid];
    float tot = 0.f;
    #pragma unroll
    for (int g=0;g<8;g++) tot += g_esum[b*8 + g];
    float cw = eT / tot;
    float ag = sigm(ifc[457]), wg = sigm(ifc[458]);

    float pscan = srt;                      // product scan over sorted usage
    #pragma unroll
    for (int o=1;o<32;o<<=1){
        float t2 = __shfl_up_sync(0xffffffffu, pscan, o);
        if (l >= o) pscan *= t2;
    }
    if (l==31) red8[wi] = pscan;
    __syncthreads();                        // A (also covers rk4 staging)
    float wpre = 1.f;
    for (int g=0; g<wi; g++) wpre *= red8[g];
    float incl = pscan * wpre;
    float prev = __shfl_up_sync(0xffffffffu, incl, 1);
    float excl = (l==0) ? wpre : prev;
    s_ex[tid] = excl;
    __syncthreads();                        // B
    float alloc = (1.f - un) * s_ex[rk];
    float wwn = wg * (ag*alloc + (1.f-ag)*cw);
    s_ww[tid] = wwn;
    __syncthreads();                        // C

    if (blockIdx.x == 0){
        float sw = wwn;
        #pragma unroll
        for (int o=16;o;o>>=1) sw += __shfl_xor_sync(0xffffffffu, sw, o);
        if (l==0) red8[wi] = sw;
        __syncthreads();
        float S = 0.f;
        #pragma unroll
        for (int g=0;g<8;g++) S += red8[g];
        g_ww[b*NN + tid] = wwn;
        g_p[par^1][b*NN + tid] = (1.f - S)*g_p[par][b*NN + tid] + wwn;
    }

    if (blockIdx.x < 32){
        int n0 = blockIdx.x*8;
        int n = n0 + wi;
        float wwr = s_ww[n];
        float* Mr = g_M + (b*NN + n)*WD;
        float m0 = Mr[l], m1 = Mr[l+32];
        m0 = m0*(1.f - wwr*ev_s[l   ]) + wwr*wv_s[l   ];
        m1 = m1*(1.f - wwr*ev_s[l+32]) + wwr*wv_s[l+32];
        Mr[l] = m0; Mr[l+32] = m1;

        float4 a = rk4[l], c = rk4[l+32];
        float ns = m0*m0 + m1*m1;
        float d0 = m0*a.x + m1*c.x;
        float d1 = m0*a.y + m1*c.y;
        float d2 = m0*a.z + m1*c.z;
        float d3 = m0*a.w + m1*c.w;
        #pragma unroll
        for (int o=16;o;o>>=1){
            ns += __shfl_xor_sync(0xffffffffu, ns, o);
            d0 += __shfl_xor_sync(0xffffffffu, d0, o);
            d1 += __shfl_xor_sync(0xffffffffu, d1, o);
            d2 += __shfl_xor_sync(0xffffffffu, d2, o);
            d3 += __shfl_xor_sync(0xffffffffu, d3, o);
        }
        if (l==0){
            float inv = 1.f/(sqrtf(ns)+FEPS);
            g_rsim[(b*RR+0)*NN+n] = d0*inv;
            g_rsim[(b*RR+1)*NN+n] = d1*inv;
            g_rsim[(b*RR+2)*NN+n] = d2*inv;
            g_rsim[(b*RR+3)*NN+n] = d3*inv;
        }

        const float* Lo = g_L[par]   + (b*NN + n)*NN;
        float*       Ln = g_L[par^1] + (b*NN + n)*NN;
        const float* pw  = g_p[par] + b*NN;
        const float* rwp = g_rw + b*RR*NN;
        float f0=0.f,f1=0.f,f2=0.f,f3=0.f;
        #pragma unroll
        for (int k=0;k<8;k++){
            int m = l + k*32;
            float lo = Lo[m];
            float ln = (1.f - wwr - s_ww[m])*lo + wwr*pw[m];
            if (m == n) ln = 0.f;
            Ln[m] = ln;
            f0 = fmaf(ln, rwp[0*NN+m], f0);
            f1 = fmaf(ln, rwp[1*NN+m], f1);
            f2 = fmaf(ln, rwp[2*NN+m], f2);
            f3 = fmaf(ln, rwp[3*NN+m], f3);
        }
        #pragma unroll
        for (int o=16;o;o>>=1){
            f0 += __shfl_xor_sync(0xffffffffu, f0, o);
            f1 += __shfl_xor_sync(0xffffffffu, f1, o);
            f2 += __shfl_xor_sync(0xffffffffu, f2, o);
            f3 += __shfl_xor_sync(0xffffffffu, f3, o);
        }
        if (l==0){
            g_fwd[(b*RR+0)*NN+n]=f0; g_fwd[(b*RR+1)*NN+n]=f1;
            g_fwd[(b*RR+2)*NN+n]=f2; g_fwd[(b*RR+3)*NN+n]=f3;
        }
    } else {
        int c = blockIdx.x - 32;
        __shared__ float4 srw[32], swr[32];
        if (tid < 32){
            int m = c*32 + tid;
            const float* rwp = g_rw + b*RR*NN;
            float4 r4 = make_float4(rwp[m], rwp[NN+m], rwp[2*NN+m], rwp[3*NN+m]);
            float wm = s_ww[m];
            srw[tid] = r4;
            swr[tid] = make_float4(wm*r4.x, wm*r4.y, wm*r4.z, wm*r4.w);
        }
        __syncthreads();
        float4 A = make_float4(0,0,0,0), Bv = make_float4(0,0,0,0);
        const float* Lo = g_L[par] + b*NN*NN + c*32*NN;
        #pragma unroll 8
        for (int q=0;q<32;q++){
            float lv = Lo[q*NN + tid];
            float4 rr = srw[q]; float4 wr = swr[q];
            A.x  = fmaf(lv, rr.x, A.x);  A.y  = fmaf(lv, rr.y, A.y);
            A.z  = fmaf(lv, rr.z, A.z);  A.w  = fmaf(lv, rr.w, A.w);
            Bv.x = fmaf(lv, wr.x, Bv.x); Bv.y = fmaf(lv, wr.y, Bv.y);
            Bv.z = fmaf(lv, wr.z, Bv.z); Bv.w = fmaf(lv, wr.w, Bv.w);
        }
        reinterpret_cast<float4*>(g_bA)[(c*BB+b)*NN + tid] = A;
        reinterpret_cast<float4*>(g_bB)[(c*BB+b)*NN + tid] = Bv;
    }
}

// ---------------- K5: bwd assembly, read softmax (rb-shift), rw_new, rv_new -----
__global__ __launch_bounds__(256) void k_read(int par){
    __shared__ float4 rwn4[256];
    __shared__ float4 red4[8];
    __shared__ float s_knd[4];
    __shared__ float partial[8*256];
    int b = blockIdx.x, tid = threadIdx.x, wi = tid>>5, l = tid&31;
    const float* ifc = g_if + b*IFW;
    const float* rwp = g_rw + b*RR*NN;

    float wwn_t = g_ww[b*NN + tid];
    float pn    = g_p[par][b*NN + tid];
    float4 r4 = make_float4(rwp[tid], rwp[NN+tid], rwp[2*NN+tid], rwp[3*NN+tid]);

    if (wi < 4){
        float k0 = ifc[wi*64 + l], k1 = ifc[wi*64 + l + 32];
        float ss = k0*k0 + k1*k1;
        #pragma unroll
        for (int o=16;o;o>>=1) ss += __shfl_xor_sync(0xffffffffu, ss, o);
        if (l==0) s_knd[wi] = sqrtf(ss) + FEPS;
    }
    float cx = wwn_t*r4.x, cy = wwn_t*r4.y, cz = wwn_t*r4.z, cw = wwn_t*r4.w;
    #pragma unroll
    for (int o=16;o;o>>=1){
        cx += __shfl_xor_sync(0xffffffffu, cx, o);
        cy += __shfl_xor_sync(0xffffffffu, cy, o);
        cz += __shfl_xor_sync(0xffffffffu, cz, o);
        cw += __shfl_xor_sync(0xffffffffu, cw, o);
    }
    if (l==0) red4[wi] = make_float4(cx,cy,cz,cw);
    __syncthreads();
    float4 C = make_float4(0,0,0,0);
    #pragma unroll
    for (int g=0;g<8;g++){
        float4 r = red4[g];
        C.x+=r.x; C.y+=r.y; C.z+=r.z; C.w+=r.w;
    }

    float4 A = make_float4(0,0,0,0), Bv = make_float4(0,0,0,0);
    #pragma unroll
    for (int c2=0;c2<8;c2++){
        float4 a = reinterpret_cast<const float4*>(g_bA)[(c2*BB+b)*NN + tid];
        float4 bb = reinterpret_cast<const float4*>(g_bB)[(c2*BB+b)*NN + tid];
        A.x+=a.x; A.y+=a.y; A.z+=a.z; A.w+=a.w;
        Bv.x+=bb.x; Bv.y+=bb.y; Bv.z+=bb.z; Bv.w+=bb.w;
    }
    float om = 1.f - wwn_t;
    float bw0 = om*A.x - Bv.x + pn*(C.x - wwn_t*r4.x);
    float bw1 = om*A.y - Bv.y + pn*(C.y - wwn_t*r4.y);
    float bw2 = om*A.z - Bv.z + pn*(C.z - wwn_t*r4.z);
    float bw3 = om*A.w - Bv.w + pn*(C.w - wwn_t*r4.w);

    float rb0 = oneplus(ifc[256]), rb1 = oneplus(ifc[257]);
    float rb2 = oneplus(ifc[258]), rb3 = oneplus(ifc[259]);
    float e0 = expf(rb0 * (g_rsim[(b*RR+0)*NN+tid] / s_knd[0] - 1.f));
    float e1 = expf(rb1 * (g_rsim[(b*RR+1)*NN+tid] / s_knd[1] - 1.f));
    float e2 = expf(rb2 * (g_rsim[(b*RR+2)*NN+tid] / s_knd[2] - 1.f));
    float e3 = expf(rb3 * (g_rsim[(b*RR+3)*NN+tid] / s_knd[3] - 1.f));
    float s0=e0,s1=e1,s2=e2,s3=e3;
    #pragma unroll
    for (int o=16;o;o>>=1){
        s0+=__shfl_xor_sync(0xffffffffu,s0,o);
        s1+=__shfl_xor_sync(0xffffffffu,s1,o);
        s2+=__shfl_xor_sync(0xffffffffu,s2,o);
        s3+=__shfl_xor_sync(0xffffffffu,s3,o);
    }
    __syncthreads();
    if (l==0) red4[wi] = make_float4(s0,s1,s2,s3);
    __syncthreads();
    float4 tv = make_float4(0,0,0,0);
    #pragma unroll
    for (int g=0;g<8;g++){
        float4 r = red4[g];
        tv.x+=r.x; tv.y+=r.y; tv.z+=r.z; tv.w+=r.w;
    }
    float rc0=e0/tv.x, rc1=e1/tv.y, rc2=e2/tv.z, rc3=e3/tv.w;

    float rm[4][3];
    #pragma unroll
    for (int r=0;r<4;r++){
        float v0=ifc[459+3*r], v1=ifc[460+3*r], v2=ifc[461+3*r];
        float mxg = fmaxf(v0, fmaxf(v1, v2));
        float a0=expf(v0-mxg), a1=expf(v1-mxg), a2=expf(v2-mxg);
        float inv = 1.f/(a0+a1+a2);
        rm[r][0]=a0*inv; rm[r][1]=a1*inv; rm[r][2]=a2*inv;
    }
    float fw0 = g_fwd[(b*RR+0)*NN+tid], fw1 = g_fwd[(b*RR+1)*NN+tid];
    float fw2 = g_fwd[(b*RR+2)*NN+tid], fw3 = g_fwd[(b*RR+3)*NN+tid];

    float w0 = rm[0][0]*bw0 + rm[0][1]*rc0 + rm[0][2]*fw0;
    float w1 = rm[1][0]*bw1 + rm[1][1]*rc1 + rm[1][2]*fw1;
    float w2 = rm[2][0]*bw2 + rm[2][1]*rc2 + rm[2][2]*fw2;
    float w3 = rm[3][0]*bw3 + rm[3][1]*rc3 + rm[3][2]*fw3;
    g_rw[(b*RR+0)*NN+tid]=w0; g_rw[(b*RR+1)*NN+tid]=w1;
    g_rw[(b*RR+2)*NN+tid]=w2; g_rw[(b*RR+3)*NN+tid]=w3;
    rwn4[tid] = make_float4(w0,w1,w2,w3);
    __syncthreads();

    float a0x=0.f,a0y=0.f,a0z=0.f,a0w=0.f;
    float a1x=0.f,a1y=0.f,a1z=0.f,a1w=0.f;
    const float* Mb = g_M + b*NN*WD;
    #pragma unroll 4
    for (int q=0;q<32;q++){
        int n = wi*32 + q;
        float lv0 = Mb[n*WD + l];
        float lv1 = Mb[n*WD + l + 32];
        float4 rn = rwn4[n];
        a0x=fmaf(lv0,rn.x,a0x); a0y=fmaf(lv0,rn.y,a0y);
        a0z=fmaf(lv0,rn.z,a0z); a0w=fmaf(lv0,rn.w,a0w);
        a1x=fmaf(lv1,rn.x,a1x); a1y=fmaf(lv1,rn.y,a1y);
        a1z=fmaf(lv1,rn.z,a1z); a1w=fmaf(lv1,rn.w,a1w);
    }
    float* pb = partial + wi*256;
    pb[0*64+l]=a0x; pb[1*64+l]=a0y; pb[2*64+l]=a0z; pb[3*64+l]=a0w;
    pb[0*64+l+32]=a1x; pb[1*64+l+32]=a1y; pb[2*64+l+32]=a1z; pb[3*64+l+32]=a1w;
    __syncthreads();
    float sum = 0.f;
    #pragma unroll
    for (int g=0;g<8;g++) sum += partial[g*256 + tid];
    g_rv[b*(RR*WD) + tid] = sum;
}

// ---------------- K6 (final step only): out = pre_out + rv @ W_memout -----------
__global__ __launch_bounds__(256) void k_out(const float* __restrict__ Wm,
                                             float* __restrict__ out, int t){
    __shared__ __align__(16) float s[BB*RR*WD];
    int tid = threadIdx.x;
    for (int i=tid;i<BB*RR*WD/4;i+=256)
        reinterpret_cast<float4*>(s)[i] = reinterpret_cast<const float4*>(g_rv)[i];
    __syncthreads();

    int kg = tid>>5, jl = tid&31;
    int j = blockIdx.x*32 + jl;
    const float* Wc = Wm + j;
    float acc[BB];
    #pragma unroll
    for (int b=0;b<BB;b++) acc[b]=0.f;
    int k0 = kg*32;
    #pragma unroll 2
    for (int kk=0; kk<32; kk+=4){
        int k = k0+kk;
        float w0 = Wc[(k+0)*OO], w1 = Wc[(k+1)*OO], w2 = Wc[(k+2)*OO], w3 = Wc[(k+3)*OO];
        #pragma unroll
        for (int b=0;b<BB;b++){
            float4 v = *reinterpret_cast<const float4*>(&s[b*(RR*WD)+k]);
            acc[b] = fmaf(v.x,w0, fmaf(v.y,w1, fmaf(v.z,w2, fmaf(v.w,w3, acc[b]))));
        }
    }
    __syncthreads();
    #pragma unroll
    for (int b=0;b<BB;b++) s[kg*512 + b*32 + jl] = acc[b];
    __syncthreads();
    for (int p=tid;p<512;p+=256){
        int b = p>>5, jj = p&31;
        int jo = blockIdx.x*32 + jj;
        float sum = g_po[b*OO + jo];
        #pragma unroll
        for (int g=0;g<8;g++) sum += s[g*512 + b*32 + jj];
        out[(t*BB + b)*OO + jo] = sum;
    }
}

// ---------------- launch --------------------------------------------------------
extern "C" void kernel_launch(void* const* d_in, const int* in_sizes, int n_in,
                              void* d_out, int out_size){
    const float* x  = (const float*)d_in[0];
    const float* Wh = (const float*)d_in[1];
    const float* bh = (const float*)d_in[2];
    const float* Wi = (const float*)d_in[3];
    const float* Wo = (const float*)d_in[4];
    const float* Wm = (const float*)d_in[5];
    float* out = (float*)d_out;

    const int smHid  = (BB*NIN + 16*256)*sizeof(float);
    const int smProj = (BB*HH  + 16*256)*sizeof(float);
    cudaFuncSetAttribute(k_hidout, cudaFuncAttributeMaxDynamicSharedMemorySize, smHid);
    cudaFuncSetAttribute(k_proj,   cudaFuncAttributeMaxDynamicSharedMemorySize, smProj);

    k_init<<<512,256>>>();
    for (int t=0;t<TT;t++){
        int par = t & 1;
        k_hidout <<<32,256,smHid>>>(x, Wh, bh, Wm, out, t);
        k_proj   <<<62,256,smProj>>>(Wo, Wi);
        k_wsim   <<<dim3(8,BB),256>>>(par);
        k_meml   <<<dim3(40,BB),256>>>(par);
        k_read   <<<BB,256>>>(par);
    }
    k_out<<<16,256>>>(Wm, out, TT-1);
}

// round 17
// speedup vs baseline: 1.0981x; 1.0981x over previous
#include <cuda_runtime.h>
#include <math.h>

#define TT  64
#define BB  16
#define II  512
#define HH  512
#define OO  512
#define NN  256
#define WD  64
#define RR  4
#define NIN 768
#define IFW 471
#define FEPS 1e-6f

// ---------------- persistent state -------------
__device__ __align__(16) float g_M [BB*NN*WD];
__device__ float g_u [BB*NN];
__device__ float g_p [2][BB*NN];
__device__ float g_ww[BB*NN];
__device__ float g_L [2][BB*NN*NN];            // double-buffered (8MB)
__device__ float g_rw[BB*RR*NN];
__device__ __align__(16) float g_rv[BB*RR*WD];
__device__ __align__(16) float g_h [BB*HH];
__device__ float g_po [BB*OO];
__device__ float g_if [BB*IFW];
__device__ float g_fwd[BB*RR*NN];
__device__ float g_esw [BB*NN];        // exp(wb*(sim-1)) per slot
__device__ float g_esum[BB*8];         // per-chunk partial sums of e
__device__ float g_alloc[BB*NN];
__device__ float g_rsim[BB*RR*NN];
__device__ __align__(16) float g_bA[8*BB*NN*4];  // bwd partial A (float4 per slot)
__device__ __align__(16) float g_bB[8*BB*NN*4];  // bwd partial B

__device__ __forceinline__ float sigm(float x){ return 1.f/(1.f+expf(-x)); }
__device__ __forceinline__ float oneplus(float x){ return 1.f + (x > 20.f ? x : log1pf(expf(x))); }

// ---------------- init ------------------
__global__ void k_init(){
    int i0 = blockIdx.x*blockDim.x + threadIdx.x;
    int st = gridDim.x*blockDim.x;
    for (int i=i0;i<BB*NN*NN;i+=st){ g_L[0][i]=0.f; g_L[1][i]=0.f; }
    for (int i=i0;i<BB*NN*WD;i+=st) g_M[i]=1e-6f;
    for (int i=i0;i<BB*NN;i+=st){
        g_u[i]=0.f; g_p[0][i]=0.f; g_p[1][i]=0.f; g_ww[i]=0.f;
    }
    for (int i=i0;i<BB*RR*NN;i+=st) g_rw[i]=0.f;
    for (int i=i0;i<BB*RR*WD;i+=st) g_rv[i]=0.f;
}

// ---------------- K1: out(t-1) = po + rv@Wm  AND  h = relu([x,rv]@W_hid + b) ----
__global__ __launch_bounds__(256) void k_hidout(const float* __restrict__ x,
        const float* __restrict__ Wh, const float* __restrict__ bh,
        const float* __restrict__ Wm, float* __restrict__ out, int t){
    extern __shared__ __align__(16) float s[];
    float* sp = s + BB*NIN;
    int tid = threadIdx.x;
    for (int i=tid;i<BB*(NIN/4);i+=256){
        int b = i/(NIN/4), k4 = i - b*(NIN/4);
        float4 v = (k4 < II/4) ? reinterpret_cast<const float4*>(x + (t*BB+b)*II)[k4]
                               : reinterpret_cast<const float4*>(g_rv + b*RR*WD)[k4 - II/4];
        reinterpret_cast<float4*>(s)[b*(NIN/4) + k4] = v;
    }
    __syncthreads();

    int kg = tid>>4, jl = tid&15;
    int j = blockIdx.x*16 + jl;

    if (t > 0){
        const float* Wc = Wm + j;
        float acc[BB];
        #pragma unroll
        for (int b=0;b<BB;b++) acc[b]=0.f;
        int k0 = kg*16;
        #pragma unroll
        for (int kk=0; kk<16; kk+=4){
            int k = k0+kk;
            float w0 = Wc[(k+0)*OO], w1 = Wc[(k+1)*OO], w2 = Wc[(k+2)*OO], w3 = Wc[(k+3)*OO];
            #pragma unroll
            for (int b=0;b<BB;b++){
                float4 v = *reinterpret_cast<const float4*>(&s[b*NIN + II + k]);
                acc[b] = fmaf(v.x,w0, fmaf(v.y,w1, fmaf(v.z,w2, fmaf(v.w,w3, acc[b]))));
            }
        }
        __syncthreads();
        #pragma unroll
        for (int b=0;b<BB;b++) sp[kg*256 + b*16 + jl] = acc[b];
        __syncthreads();
        {
            int p = tid;
            int b = p>>4, jj = p&15;
            int jo = blockIdx.x*16 + jj;
            float sum = g_po[b*OO + jo];
            #pragma unroll
            for (int g=0;g<16;g++) sum += sp[g*256 + p];
            out[((t-1)*BB + b)*OO + jo] = sum;
        }
        __syncthreads();
    }

    const float* Wc = Wh + j;
    float acc[BB];
    #pragma unroll
    for (int b=0;b<BB;b++) acc[b]=0.f;
    int k0 = kg*48;
    #pragma unroll 3
    for (int kk=0; kk<48; kk+=4){
        int k = k0+kk;
        float w0 = Wc[(k+0)*HH], w1 = Wc[(k+1)*HH], w2 = Wc[(k+2)*HH], w3 = Wc[(k+3)*HH];
        #pragma unroll
        for (int b=0;b<BB;b++){
            float4 v = *reinterpret_cast<const float4*>(&s[b*NIN+k]);
            acc[b] = fmaf(v.x,w0, fmaf(v.y,w1, fmaf(v.z,w2, fmaf(v.w,w3, acc[b]))));
        }
    }
    __syncthreads();
    #pragma unroll
    for (int b=0;b<BB;b++) sp[kg*256 + b*16 + jl] = acc[b];
    __syncthreads();
    {
        int p = tid;
        int b = p>>4, jj = p&15;
        int jo = blockIdx.x*16 + jj;
        float sum = bh[jo];
        #pragma unroll
        for (int g=0;g<16;g++) sum += sp[g*256 + p];
        g_h[b*HH + jo] = fmaxf(sum, 0.f);
    }
}

// ---------------- K2: proj GEMM (CTAs 0..61) + alloc pipeline (CTAs 62..77) -----
__global__ __launch_bounds__(256) void k_proj(const float* __restrict__ Wo,
                                              const float* __restrict__ Wi){
    extern __shared__ __align__(16) float s[];
    int tid = threadIdx.x, wi = tid>>5, l = tid&31;

    if (blockIdx.x < 62){
        float* sp = s + BB*HH;
        for (int i=tid;i<BB*HH/4;i+=256)
            reinterpret_cast<float4*>(s)[i] = reinterpret_cast<const float4*>(g_h)[i];
        __syncthreads();

        int kg = tid>>4, jl = tid&15;
        int j = blockIdx.x*16 + jl;
        const float* Wc; int stride;
        if (j < OO){ Wc = Wo + j; stride = OO; }
        else { int jj = j - OO; if (jj > IFW-1) jj = IFW-1; Wc = Wi + jj; stride = IFW; }
        float acc[BB];
        #pragma unroll
        for (int b=0;b<BB;b++) acc[b]=0.f;
        int k0 = kg*32;
        #pragma unroll 2
        for (int kk=0; kk<32; kk+=4){
            int k = k0+kk;
            float w0 = Wc[(k+0)*stride], w1 = Wc[(k+1)*stride];
            float w2 = Wc[(k+2)*stride], w3 = Wc[(k+3)*stride];
            #pragma unroll
            for (int b=0;b<BB;b++){
                float4 v = *reinterpret_cast<const float4*>(&s[b*HH+k]);
                acc[b] = fmaf(v.x,w0, fmaf(v.y,w1, fmaf(v.z,w2, fmaf(v.w,w3, acc[b]))));
            }
        }
        __syncthreads();
        #pragma unroll
        for (int b=0;b<BB;b++) sp[kg*256 + b*16 + jl] = acc[b];
        __syncthreads();
        {
            int p = tid;
            int b = p>>4, jj = p&15;
            int jo = blockIdx.x*16 + jj;
            float sum = 0.f;
            #pragma unroll
            for (int g=0;g<16;g++) sum += sp[g*256 + p];
            if (jo < OO) g_po[b*OO + jo] = sum;
            else if (jo - OO < IFW) g_if[b*IFW + (jo-OO)] = sum;
        }
    } else {
        // ---- alloc pipeline for batch b: fg dots -> usage -> rank -> cumprod
        int b = blockIdx.x - 62;
        float* sh_h = s;                               // 512 floats
        float* shB  = s + 512;                         // 256
        float* shC  = s + 768;                         // 256
        float* sfg  = s + 1024;                        // 4
        float* prt  = s + 1032;                        // 8
        unsigned long long* sk64 =
            reinterpret_cast<unsigned long long*>(s + 1040); // 256 u64 (aligned: s is 16B-aligned, 1040*4=4160 16B-aligned)
        float* red8 = s + 1552;

        for (int k=tid;k<HH;k+=256) sh_h[k] = g_h[b*HH + k];
        __syncthreads();
        // fg dots: 2 warps per column r = wi>>1; halves by (wi&1)
        {
            int r = wi>>1, half = wi&1;
            float sum = 0.f;
            #pragma unroll
            for (int q=0;q<8;q++){
                int k = half*256 + q*32 + l;
                sum += sh_h[k] * Wi[k*IFW + 453 + r];
            }
            #pragma unroll
            for (int o=16;o;o>>=1) sum += __shfl_xor_sync(0xffffffffu, sum, o);
            if (l==0) prt[wi] = sum;
        }
        __syncthreads();
        if (tid < 4) sfg[tid] = sigm(prt[2*tid] + prt[2*tid+1]);
        __syncthreads();

        float fg0 = sfg[0], fg1 = sfg[1], fg2 = sfg[2], fg3 = sfg[3];
        float u   = g_u [b*NN + tid];
        float wwo = g_ww[b*NN + tid];
        float ret = (1.f - fg0*g_rw[(b*RR+0)*NN+tid])
                  * (1.f - fg1*g_rw[(b*RR+1)*NN+tid])
                  * (1.f - fg2*g_rw[(b*RR+2)*NN+tid])
                  * (1.f - fg3*g_rw[(b*RR+3)*NN+tid]);
        float un = (u + wwo - u*wwo) * ret;
        g_u[b*NN + tid] = un;
        unsigned int bits = __float_as_uint(un);
        bits ^= (unsigned int)(((int)bits >> 31)) | 0x80000000u;
        sk64[tid] = ((unsigned long long)bits << 32) | (unsigned int)tid;
        __syncthreads();
        unsigned long long mykey = sk64[tid];
        int rank = 0;
        const ulonglong2* p2 = reinterpret_cast<const ulonglong2*>(sk64);
        #pragma unroll 8
        for (int j2=0;j2<128;j2++){
            ulonglong2 v = p2[j2];
            rank += (int)(v.x < mykey) + (int)(v.y < mykey);
        }
        shB[rank] = un;
        __syncthreads();
        float pscan = shB[tid];
        #pragma unroll
        for (int o=1;o<32;o<<=1){
            float t2 = __shfl_up_sync(0xffffffffu, pscan, o);
            if (l >= o) pscan *= t2;
        }
        if (l==31) red8[wi] = pscan;
        __syncthreads();
        float wpre = 1.f;
        for (int g=0; g<wi; g++) wpre *= red8[g];
        float incl = pscan * wpre;
        float prev = __shfl_up_sync(0xffffffffu, incl, 1);
        float excl = (l==0) ? wpre : prev;
        shC[tid] = excl;
        __syncthreads();
        g_alloc[b*NN + tid] = (1.f - un) * shC[rank];
    }
}

// ---------------- K3: write-content e=exp(wb(sim-1)) + chunk partial sums -------
// grid (8,16) x 256; warp handles 4 rows, interleaved butterfly.
__global__ __launch_bounds__(256) void k_wsim(){
    int b = blockIdx.y, c = blockIdx.x;
    int tid = threadIdx.x, wi = tid>>5, l = tid&31;
    __shared__ float wk_s[64];
    __shared__ float red8[8];
    const float* ifc = g_if + b*IFW;
    if (tid < 64) wk_s[tid] = ifc[260+tid];
    __syncthreads();
    float k0 = wk_s[l], k1 = wk_s[l+32];
    float kk = k0*k0 + k1*k1;
    int nb = c*32 + wi*4;
    float ns[4], dt[4];
    #pragma unroll
    for (int i=0;i<4;i++){
        const float* Mr = g_M + (b*NN + nb + i)*WD;
        float m0 = Mr[l], m1 = Mr[l+32];
        ns[i] = m0*m0 + m1*m1;
        dt[i] = m0*k0 + m1*k1;
    }
    #pragma unroll
    for (int o=16;o;o>>=1){
        kk += __shfl_xor_sync(0xffffffffu, kk, o);
        #pragma unroll
        for (int i=0;i<4;i++){
            ns[i] += __shfl_xor_sync(0xffffffffu, ns[i], o);
            dt[i] += __shfl_xor_sync(0xffffffffu, dt[i], o);
        }
    }
    if (l==0){
        float wb = oneplus(ifc[324]);
        float dk = sqrtf(kk) + FEPS;
        float psum = 0.f;
        #pragma unroll
        for (int i=0;i<4;i++){
            float sim = dt[i] / ((sqrtf(ns[i])+FEPS) * dk);
            float e = expf(wb * (sim - 1.f));
            g_esw[b*NN + nb + i] = e;
            psum += e;
        }
        red8[wi] = psum;
    }
    __syncthreads();
    if (tid == 0){
        float tot = 0.f;
        #pragma unroll
        for (int g=0;g<8;g++) tot += red8[g];
        g_esum[b*8 + c] = tot;
    }
}

// ---------------- K4: ww prologue + M update + read sims + L rows + fwd + bwd ---
// grid (40,16) x 256. x<32: warp-per-L-row. x>=32: bwd chunk c=x-32.
__global__ __launch_bounds__(256) void k_meml(int par){
    int b = blockIdx.y;
    int tid = threadIdx.x, wi = tid>>5, l = tid&31;
    const float* ifc = g_if + b*IFW;
    __shared__ float s_ww[256];
    __shared__ float red8[8];
    __shared__ float4 rk4[64];
    __shared__ float ev_s[64], wv_s[64];

    // stage iface vectors early (overlaps prologue)
    if (blockIdx.x < 32 && tid < 64){
        rk4[tid] = make_float4(ifc[tid], ifc[64+tid], ifc[128+tid], ifc[192+tid]);
        ev_s[tid] = sigm(ifc[325 + tid]);
        wv_s[tid] = ifc[389 + tid];
    }
    // ---- ww prologue (no reductions): cw = e/Σe from precomputed partials
    {
        float eT = g_esw[b*NN + tid];
        float tot = 0.f;
        #pragma unroll
        for (int g=0;g<8;g++) tot += g_esum[b*8 + g];
        float cw = eT / tot;
        float ag = sigm(ifc[457]), wg = sigm(ifc[458]);
        float wwn = wg * (ag*g_alloc[b*NN + tid] + (1.f-ag)*cw);
        s_ww[tid] = wwn;
    }
    __syncthreads();

    if (blockIdx.x == 0){
        float wwn = s_ww[tid];
        float sw = wwn;
        #pragma unroll
        for (int o=16;o;o>>=1) sw += __shfl_xor_sync(0xffffffffu, sw, o);
        if (l==0) red8[wi] = sw;
        __syncthreads();
        float S = 0.f;
        #pragma unroll
        for (int g=0;g<8;g++) S += red8[g];
        g_ww[b*NN + tid] = wwn;
        g_p[par^1][b*NN + tid] = (1.f - S)*g_p[par][b*NN + tid] + wwn;
    }

    if (blockIdx.x < 32){
        int n0 = blockIdx.x*8;
        int n = n0 + wi;
        float wwn = s_ww[n];
        float* Mr = g_M + (b*NN + n)*WD;
        float m0 = Mr[l], m1 = Mr[l+32];
        m0 = m0*(1.f - wwn*ev_s[l   ]) + wwn*wv_s[l   ];
        m1 = m1*(1.f - wwn*ev_s[l+32]) + wwn*wv_s[l+32];
        Mr[l] = m0; Mr[l+32] = m1;

        float4 a = rk4[l], c = rk4[l+32];
        float ns = m0*m0 + m1*m1;
        float d0 = m0*a.x + m1*c.x;
        float d1 = m0*a.y + m1*c.y;
        float d2 = m0*a.z + m1*c.z;
        float d3 = m0*a.w + m1*c.w;
        #pragma unroll
        for (int o=16;o;o>>=1){
            ns += __shfl_xor_sync(0xffffffffu, ns, o);
            d0 += __shfl_xor_sync(0xffffffffu, d0, o);
            d1 += __shfl_xor_sync(0xffffffffu, d1, o);
            d2 += __shfl_xor_sync(0xffffffffu, d2, o);
            d3 += __shfl_xor_sync(0xffffffffu, d3, o);
        }
        if (l==0){
            float inv = 1.f/(sqrtf(ns)+FEPS);
            g_rsim[(b*RR+0)*NN+n] = d0*inv;
            g_rsim[(b*RR+1)*NN+n] = d1*inv;
            g_rsim[(b*RR+2)*NN+n] = d2*inv;
            g_rsim[(b*RR+3)*NN+n] = d3*inv;
        }

        const float* Lo = g_L[par]   + (b*NN + n)*NN;
        float*       Ln = g_L[par^1] + (b*NN + n)*NN;
        const float* pw  = g_p[par] + b*NN;
        const float* rwp = g_rw + b*RR*NN;
        float f0=0.f,f1=0.f,f2=0.f,f3=0.f;
        #pragma unroll
        for (int k=0;k<8;k++){
            int m = l + k*32;
            float lo = Lo[m];
            float ln = (1.f - wwn - s_ww[m])*lo + wwn*pw[m];
            if (m == n) ln = 0.f;
            Ln[m] = ln;
            f0 = fmaf(ln, rwp[0*NN+m], f0);
            f1 = fmaf(ln, rwp[1*NN+m], f1);
            f2 = fmaf(ln, rwp[2*NN+m], f2);
            f3 = fmaf(ln, rwp[3*NN+m], f3);
        }
        #pragma unroll
        for (int o=16;o;o>>=1){
            f0 += __shfl_xor_sync(0xffffffffu, f0, o);
            f1 += __shfl_xor_sync(0xffffffffu, f1, o);
            f2 += __shfl_xor_sync(0xffffffffu, f2, o);
            f3 += __shfl_xor_sync(0xffffffffu, f3, o);
        }
        if (l==0){
            g_fwd[(b*RR+0)*NN+n]=f0; g_fwd[(b*RR+1)*NN+n]=f1;
            g_fwd[(b*RR+2)*NN+n]=f2; g_fwd[(b*RR+3)*NN+n]=f3;
        }
    } else {
        int c = blockIdx.x - 32;
        __shared__ float4 srw[32], swr[32];
        if (tid < 32){
            int m = c*32 + tid;
            const float* rwp = g_rw + b*RR*NN;
            float4 r4 = make_float4(rwp[m], rwp[NN+m], rwp[2*NN+m], rwp[3*NN+m]);
            float wm = s_ww[m];
            srw[tid] = r4;
            swr[tid] = make_float4(wm*r4.x, wm*r4.y, wm*r4.z, wm*r4.w);
        }
        __syncthreads();
        float4 A = make_float4(0,0,0,0), Bv = make_float4(0,0,0,0);
        const float* Lo = g_L[par] + b*NN*NN + c*32*NN;
        #pragma unroll 8
        for (int q=0;q<32;q++){
            float lv = Lo[q*NN + tid];
            float4 rr = srw[q]; float4 wr = swr[q];
            A.x  = fmaf(lv, rr.x, A.x);  A.y  = fmaf(lv, rr.y, A.y);
            A.z  = fmaf(lv, rr.z, A.z);  A.w  = fmaf(lv, rr.w, A.w);
            Bv.x = fmaf(lv, wr.x, Bv.x); Bv.y = fmaf(lv, wr.y, Bv.y);
            Bv.z = fmaf(lv, wr.z, Bv.z); Bv.w = fmaf(lv, wr.w, Bv.w);
        }
        reinterpret_cast<float4*>(g_bA)[(c*BB+b)*NN + tid] = A;
        reinterpret_cast<float4*>(g_bB)[(c*BB+b)*NN + tid] = Bv;
    }
}

// ---------------- K5: bwd assembly, read softmax (rb-shift), rw_new, rv_new -----
__global__ __launch_bounds__(256) void k_read(int par){
    __shared__ float4 rwn4[256];
    __shared__ float4 red4[8];
    __shared__ float s_knd[4];
    __shared__ float partial[8*256];
    int b = blockIdx.x, tid = threadIdx.x, wi = tid>>5, l = tid&31;
    const float* ifc = g_if + b*IFW;
    const float* rwp = g_rw + b*RR*NN;

    float wwn_t = g_ww[b*NN + tid];
    float pn    = g_p[par][b*NN + tid];
    float4 r4 = make_float4(rwp[tid], rwp[NN+tid], rwp[2*NN+tid], rwp[3*NN+tid]);

    if (wi < 4){
        float k0 = ifc[wi*64 + l], k1 = ifc[wi*64 + l + 32];
        float ss = k0*k0 + k1*k1;
        #pragma unroll
        for (int o=16;o;o>>=1) ss += __shfl_xor_sync(0xffffffffu, ss, o);
        if (l==0) s_knd[wi] = sqrtf(ss) + FEPS;
    }
    float cx = wwn_t*r4.x, cy = wwn_t*r4.y, cz = wwn_t*r4.z, cw = wwn_t*r4.w;
    #pragma unroll
    for (int o=16;o;o>>=1){
        cx += __shfl_xor_sync(0xffffffffu, cx, o);
        cy += __shfl_xor_sync(0xffffffffu, cy, o);
        cz += __shfl_xor_sync(0xffffffffu, cz, o);
        cw += __shfl_xor_sync(0xffffffffu, cw, o);
    }
    if (l==0) red4[wi] = make_float4(cx,cy,cz,cw);
    __syncthreads();
    float4 C = make_float4(0,0,0,0);
    #pragma unroll
    for (int g=0;g<8;g++){
        float4 r = red4[g];
        C.x+=r.x; C.y+=r.y; C.z+=r.z; C.w+=r.w;
    }

    float4 A = make_float4(0,0,0,0), Bv = make_float4(0,0,0,0);
    #pragma unroll
    for (int c2=0;c2<8;c2++){
        float4 a = reinterpret_cast<const float4*>(g_bA)[(c2*BB+b)*NN + tid];
        float4 bb = reinterpret_cast<const float4*>(g_bB)[(c2*BB+b)*NN + tid];
        A.x+=a.x; A.y+=a.y; A.z+=a.z; A.w+=a.w;
        Bv.x+=bb.x; Bv.y+=bb.y; Bv.z+=bb.z; Bv.w+=bb.w;
    }
    float om = 1.f - wwn_t;
    float bw0 = om*A.x - Bv.x + pn*(C.x - wwn_t*r4.x);
    float bw1 = om*A.y - Bv.y + pn*(C.y - wwn_t*r4.y);
    float bw2 = om*A.z - Bv.z + pn*(C.z - wwn_t*r4.z);
    float bw3 = om*A.w - Bv.w + pn*(C.w - wwn_t*r4.w);

    float rb0 = oneplus(ifc[256]), rb1 = oneplus(ifc[257]);
    float rb2 = oneplus(ifc[258]), rb3 = oneplus(ifc[259]);
    float e0 = expf(rb0 * (g_rsim[(b*RR+0)*NN+tid] / s_knd[0] - 1.f));
    float e1 = expf(rb1 * (g_rsim[(b*RR+1)*NN+tid] / s_knd[1] - 1.f));
    float e2 = expf(rb2 * (g_rsim[(b*RR+2)*NN+tid] / s_knd[2] - 1.f));
    float e3 = expf(rb3 * (g_rsim[(b*RR+3)*NN+tid] / s_knd[3] - 1.f));
    float s0=e0,s1=e1,s2=e2,s3=e3;
    #pragma unroll
    for (int o=16;o;o>>=1){
        s0+=__shfl_xor_sync(0xffffffffu,s0,o);
        s1+=__shfl_xor_sync(0xffffffffu,s1,o);
        s2+=__shfl_xor_sync(0xffffffffu,s2,o);
        s3+=__shfl_xor_sync(0xffffffffu,s3,o);
    }
    __syncthreads();
    if (l==0) red4[wi] = make_float4(s0,s1,s2,s3);
    __syncthreads();
    float4 tv = make_float4(0,0,0,0);
    #pragma unroll
    for (int g=0;g<8;g++){
        float4 r = red4[g];
        tv.x+=r.x; tv.y+=r.y; tv.z+=r.z; tv.w+=r.w;
    }
    float rc0=e0/tv.x, rc1=e1/tv.y, rc2=e2/tv.z, rc3=e3/tv.w;

    float rm[4][3];
    #pragma unroll
    for (int r=0;r<4;r++){
        float v0=ifc[459+3*r], v1=ifc[460+3*r], v2=ifc[461+3*r];
        float mxg = fmaxf(v0, fmaxf(v1, v2));
        float a0=expf(v0-mxg), a1=expf(v1-mxg), a2=expf(v2-mxg);
        float inv = 1.f/(a0+a1+a2);
        rm[r][0]=a0*inv; rm[r][1]=a1*inv; rm[r][2]=a2*inv;
    }
    float fw0 = g_fwd[(b*RR+0)*NN+tid], fw1 = g_fwd[(b*RR+1)*NN+tid];
    float fw2 = g_fwd[(b*RR+2)*NN+tid], fw3 = g_fwd[(b*RR+3)*NN+tid];

    float w0 = rm[0][0]*bw0 + rm[0][1]*rc0 + rm[0][2]*fw0;
    float w1 = rm[1][0]*bw1 + rm[1][1]*rc1 + rm[1][2]*fw1;
    float w2 = rm[2][0]*bw2 + rm[2][1]*rc2 + rm[2][2]*fw2;
    float w3 = rm[3][0]*bw3 + rm[3][1]*rc3 + rm[3][2]*fw3;
    g_rw[(b*RR+0)*NN+tid]=w0; g_rw[(b*RR+1)*NN+tid]=w1;
    g_rw[(b*RR+2)*NN+tid]=w2; g_rw[(b*RR+3)*NN+tid]=w3;
    rwn4[tid] = make_float4(w0,w1,w2,w3);
    __syncthreads();

    float a0x=0.f,a0y=0.f,a0z=0.f,a0w=0.f;
    float a1x=0.f,a1y=0.f,a1z=0.f,a1w=0.f;
    const float* Mb = g_M + b*NN*WD;
    #pragma unroll 4
    for (int q=0;q<32;q++){
        int n = wi*32 + q;
        float lv0 = Mb[n*WD + l];
        float lv1 = Mb[n*WD + l + 32];
        float4 rn = rwn4[n];
        a0x=fmaf(lv0,rn.x,a0x); a0y=fmaf(lv0,rn.y,a0y);
        a0z=fmaf(lv0,rn.z,a0z); a0w=fmaf(lv0,rn.w,a0w);
        a1x=fmaf(lv1,rn.x,a1x); a1y=fmaf(lv1,rn.y,a1y);
        a1z=fmaf(lv1,rn.z,a1z); a1w=fmaf(lv1,rn.w,a1w);
    }
    float* pb = partial + wi*256;
    pb[0*64+l]=a0x; pb[1*64+l]=a0y; pb[2*64+l]=a0z; pb[3*64+l]=a0w;
    pb[0*64+l+32]=a1x; pb[1*64+l+32]=a1y; pb[2*64+l+32]=a1z; pb[3*64+l+32]=a1w;
    __syncthreads();
    float sum = 0.f;
    #pragma unroll
    for (int g=0;g<8;g++) sum += partial[g*256 + tid];
    g_rv[b*(RR*WD) + tid] = sum;
}

// ---------------- K6 (final step only): out = pre_out + rv @ W_memout -----------
__global__ __launch_bounds__(256) void k_out(const float* __restrict__ Wm,
                                             float* __restrict__ out, int t){
    __shared__ __align__(16) float s[BB*RR*WD];
    int tid = threadIdx.x;
    for (int i=tid;i<BB*RR*WD/4;i+=256)
        reinterpret_cast<float4*>(s)[i] = reinterpret_cast<const float4*>(g_rv)[i];
    __syncthreads();

    int kg = tid>>5, jl = tid&31;
    int j = blockIdx.x*32 + jl;
    const float* Wc = Wm + j;
    float acc[BB];
    #pragma unroll
    for (int b=0;b<BB;b++) acc[b]=0.f;
    int k0 = kg*32;
    #pragma unroll 2
    for (int kk=0; kk<32; kk+=4){
        int k = k0+kk;
        float w0 = Wc[(k+0)*OO], w1 = Wc[(k+1)*OO], w2 = Wc[(k+2)*OO], w3 = Wc[(k+3)*OO];
        #pragma unroll
        for (int b=0;b<BB;b++){
            float4 v = *reinterpret_cast<const float4*>(&s[b*(RR*WD)+k]);
            acc[b] = fmaf(v.x,w0, fmaf(v.y,w1, fmaf(v.z,w2, fmaf(v.w,w3, acc[b]))));
        }
    }
    __syncthreads();
    #pragma unroll
    for (int b=0;b<BB;b++) s[kg*512 + b*32 + jl] = acc[b];
    __syncthreads();
    for (int p=tid;p<512;p+=256){
        int b = p>>5, jj = p&31;
        int jo = blockIdx.x*32 + jj;
        float sum = g_po[b*OO + jo];
        #pragma unroll
        for (int g=0;g<8;g++) sum += s[g*512 + b*32 + jj];
        out[(t*BB + b)*OO + jo] = sum;
    }
}

// ---------------- launch --------------------------------------------------------
extern "C" void kernel_launch(void* const* d_in, const int* in_sizes, int n_in,
                              void* d_out, int out_size){
    const float* x  = (const float*)d_in[0];
    const float* Wh = (const float*)d_in[1];
    const float* bh = (const float*)d_in[2];
    const float* Wi = (const float*)d_in[3];
    const float* Wo = (const float*)d_in[4];
    const float* Wm = (const float*)d_in[5];
    float* out = (float*)d_out;

    const int smHid  = (BB*NIN + 16*256)*sizeof(float);
    const int smProj = (BB*HH  + 16*256)*sizeof(float);
    cudaFuncSetAttribute(k_hidout, cudaFuncAttributeMaxDynamicSharedMemorySize, smHid);
    cudaFuncSetAttribute(k_proj,   cudaFuncAttributeMaxDynamicSharedMemorySize, smProj);

    k_init<<<512,256>>>();
    for (int t=0;t<TT;t++){
        int par = t & 1;
        k_hidout <<<32,256,smHid>>>(x, Wh, bh, Wm, out, t);
        k_proj   <<<78,256,smProj>>>(Wo, Wi);
        k_wsim   <<<dim3(8,BB),256>>>();
        k_meml   <<<dim3(40,BB),256>>>(par);
        k_read   <<<BB,256>>>(par);
    }
    k_out<<<16,256>>>(Wm, out, TT-1);
}